// round 2
// baseline (speedup 1.0000x reference)
#include <cuda_runtime.h>
#include <math.h>

#define D_MODEL 1024
#define N_HEAD  16
#define D_HEAD  64
#define N_CTX   2048
#define BATCH   2
#define MTOT    (BATCH * N_CTX)   /* 4096 rows */

// ---------------- scratch (static device globals; no allocation) ----------------
__device__ float g_q[MTOT * D_MODEL];
__device__ float g_k[MTOT * D_MODEL];
__device__ float g_v[MTOT * D_MODEL];
__device__ float g_z[MTOT * D_MODEL];
__device__ float g_cos[N_CTX * 32];
__device__ float g_sin[N_CTX * 32];

// ---------------- RoPE table (fp64 sincos; immune to fast-math) ----------------
__global__ void rope_cache_kernel() {
    int i = blockIdx.x * blockDim.x + threadIdx.x;   // 0 .. 65535
    int t = i >> 5;
    int j = i & 31;
    // inv_freq = base^(-j/32), quantized to fp32 like the reference
    float invf = (float)pow(10000.0, -(double)j / 32.0);
    double ang = (double)t * (double)invf;           // reference's fp32 emb, full precision here
    double sv, cv;
    sincos(ang, &sv, &cv);
    g_cos[i] = (float)cv;
    g_sin[i] = (float)sv;
}

// ---------------- generic C = A * B^T (+bias[n]) (+res[m,n]) ----------------
// A: [M,K] row-major, B: [N,K] row-major (both K-contiguous)
__global__ __launch_bounds__(256, 2)
void gemm_nt_kernel(const float* __restrict__ A, const float* __restrict__ Bm,
                    const float* __restrict__ bias, const float* __restrict__ res,
                    float* __restrict__ C, int M, int N, int K)
{
    __shared__ float As[16][132];   // transposed: As[k][m]
    __shared__ float Bs[16][132];   // transposed: Bs[k][n]

    const int tid = threadIdx.x;
    const int tx = tid & 15, ty = tid >> 4;
    const int m0 = blockIdx.y * 128, n0 = blockIdx.x * 128;

    const int lr = tid >> 2;          // 0..63
    const int lc = (tid & 3) << 2;    // 0,4,8,12

    const float* Ap = A  + (size_t)(m0 + lr) * K + lc;
    const float* Bp = Bm + (size_t)(n0 + lr) * K + lc;

    float acc[8][8];
#pragma unroll
    for (int i = 0; i < 8; i++)
#pragma unroll
        for (int j = 0; j < 8; j++) acc[i][j] = 0.f;

    for (int kt = 0; kt < K; kt += 16) {
        float4 a0 = *(const float4*)(Ap + kt);
        float4 a1 = *(const float4*)(Ap + (size_t)64 * K + kt);
        float4 b0 = *(const float4*)(Bp + kt);
        float4 b1 = *(const float4*)(Bp + (size_t)64 * K + kt);
        __syncthreads();
        As[lc + 0][lr] = a0.x; As[lc + 1][lr] = a0.y; As[lc + 2][lr] = a0.z; As[lc + 3][lr] = a0.w;
        As[lc + 0][lr + 64] = a1.x; As[lc + 1][lr + 64] = a1.y; As[lc + 2][lr + 64] = a1.z; As[lc + 3][lr + 64] = a1.w;
        Bs[lc + 0][lr] = b0.x; Bs[lc + 1][lr] = b0.y; Bs[lc + 2][lr] = b0.z; Bs[lc + 3][lr] = b0.w;
        Bs[lc + 0][lr + 64] = b1.x; Bs[lc + 1][lr + 64] = b1.y; Bs[lc + 2][lr + 64] = b1.z; Bs[lc + 3][lr + 64] = b1.w;
        __syncthreads();
#pragma unroll
        for (int kk = 0; kk < 16; ++kk) {
            float ar[8], br[8];
            *(float4*)&ar[0] = *(const float4*)&As[kk][ty * 8];
            *(float4*)&ar[4] = *(const float4*)&As[kk][ty * 8 + 4];
            *(float4*)&br[0] = *(const float4*)&Bs[kk][tx * 8];
            *(float4*)&br[4] = *(const float4*)&Bs[kk][tx * 8 + 4];
#pragma unroll
            for (int i = 0; i < 8; i++)
#pragma unroll
                for (int j = 0; j < 8; j++)
                    acc[i][j] = fmaf(ar[i], br[j], acc[i][j]);
        }
    }

    // epilogue: coalesced float4 stores, optional bias / residual
    float4 bb0 = make_float4(0.f, 0.f, 0.f, 0.f), bb1 = bb0;
    if (bias) {
        bb0 = *(const float4*)&bias[n0 + tx * 8];
        bb1 = *(const float4*)&bias[n0 + tx * 8 + 4];
    }
#pragma unroll
    for (int i = 0; i < 8; i++) {
        int m = m0 + ty * 8 + i;
        float* Crow = C + (size_t)m * N + n0 + tx * 8;
        float4 v0 = make_float4(acc[i][0] + bb0.x, acc[i][1] + bb0.y, acc[i][2] + bb0.z, acc[i][3] + bb0.w);
        float4 v1 = make_float4(acc[i][4] + bb1.x, acc[i][5] + bb1.y, acc[i][6] + bb1.z, acc[i][7] + bb1.w);
        if (res) {
            const float* Rrow = res + (size_t)m * N + n0 + tx * 8;
            float4 r0 = *(const float4*)Rrow;
            float4 r1 = *(const float4*)(Rrow + 4);
            v0.x += r0.x; v0.y += r0.y; v0.z += r0.z; v0.w += r0.w;
            v1.x += r1.x; v1.y += r1.y; v1.z += r1.z; v1.w += r1.w;
        }
        *(float4*)Crow = v0;
        *(float4*)(Crow + 4) = v1;
    }
}

// ---------------- fused RMSNorm + RoPE, in-place on q and k ----------------
// One warp per (b,s,h) row of 64; lane i owns the (2i, 2i+1) rotation pair.
__global__ __launch_bounds__(256)
void norm_rope_kernel(float* __restrict__ q, float* __restrict__ k,
                      const float* __restrict__ w)
{
    int gw = (blockIdx.x * blockDim.x + threadIdx.x) >> 5;   // global warp: 0 .. 131071
    int lane = threadIdx.x & 31;
    int which = gw & 1;
    int row = gw >> 1;                                       // 0 .. 65535 = (b*S + s)*H + h
    float* ptr = which ? k : q;

    size_t base = (size_t)(row >> 4) * D_MODEL + (size_t)(row & 15) * 64;
    int s = (row >> 4) & (N_CTX - 1);

    float2 xv = *(float2*)&ptr[base + lane * 2];
    float ss = xv.x * xv.x + xv.y * xv.y;
#pragma unroll
    for (int o = 16; o; o >>= 1) ss += __shfl_xor_sync(0xffffffffu, ss, o);
    float r = rsqrtf(ss * (1.0f / 64.0f) + 1.1920929e-07f);

    float y0 = xv.x * r * w[lane * 2];
    float y1 = xv.y * r * w[lane * 2 + 1];

    int j0 = (2 * lane) & 31;
    int j1 = (2 * lane + 1) & 31;
    float c0 = g_cos[s * 32 + j0], s0 = g_sin[s * 32 + j0];
    float c1 = g_cos[s * 32 + j1], s1 = g_sin[s * 32 + j1];

    float2 o;
    o.x = y0 * c0 - y1 * s0;
    o.y = y1 * c1 + y0 * s1;
    *(float2*)&ptr[base + lane * 2] = o;
}

// ---------------- fused quadratic causal attention ----------------
// Per block: one (b,h,q-tile of 64). Loop k-tiles up to the diagonal.
// S = Q K^T ; P = (S/64)^2 * causal ; Z += P V. No softmax -> no running stats.
#define ATTN_SMEM ((4096 * 3 + 64 * 68) * 4)   /* 66560 B */

__global__ __launch_bounds__(256)
void attn_kernel(const float* __restrict__ Q, const float* __restrict__ Kb,
                 const float* __restrict__ V, float* __restrict__ Z)
{
    extern __shared__ float smf[];
    float* Qs = smf;            // [64][64] d-major: Qs[d*64 + qi]
    float* Ks = smf + 4096;     // [64][64] d-major: Ks[d*64 + ki]
    float* Vs = smf + 8192;     // [64][64] k-major: Vs[ki*64 + d]
    float* Ps = smf + 12288;    // [64][68] q-major: Ps[qi*68 + ki]

    const int tid = threadIdx.x;
    const int tx = tid & 15, ty = tid >> 4;
    const int bh = blockIdx.y;
    const int b = bh >> 4, h = bh & 15;
    const int qt = (int)gridDim.x - 1 - (int)blockIdx.x;   // big tiles launch first

    const int lrow = tid >> 4;           // 0..15
    const int lcol = (tid & 15) << 2;    // 0..60
    const size_t basebs = (size_t)(b * N_CTX) * D_MODEL + h * 64;

    // load Q tile, transposed to d-major
#pragma unroll
    for (int r = 0; r < 4; ++r) {
        int row = lrow + 16 * r;
        int sq = qt * 64 + row;
        float4 qv = *(const float4*)&Q[basebs + (size_t)sq * D_MODEL + lcol];
        Qs[(lcol + 0) * 64 + row] = qv.x;
        Qs[(lcol + 1) * 64 + row] = qv.y;
        Qs[(lcol + 2) * 64 + row] = qv.z;
        Qs[(lcol + 3) * 64 + row] = qv.w;
    }

    float zacc[4][4];
#pragma unroll
    for (int i = 0; i < 4; i++)
#pragma unroll
        for (int j = 0; j < 4; j++) zacc[i][j] = 0.f;

    const float inv64 = 1.0f / 64.0f;

    for (int kt = 0; kt <= qt; ++kt) {
        __syncthreads();   // previous iter's consumers done with Ks/Vs/Ps (also covers Q load, iter 0)
#pragma unroll
        for (int r = 0; r < 4; ++r) {
            int row = lrow + 16 * r;
            int sk = kt * 64 + row;
            float4 kv = *(const float4*)&Kb[basebs + (size_t)sk * D_MODEL + lcol];
            Ks[(lcol + 0) * 64 + row] = kv.x;
            Ks[(lcol + 1) * 64 + row] = kv.y;
            Ks[(lcol + 2) * 64 + row] = kv.z;
            Ks[(lcol + 3) * 64 + row] = kv.w;
            float4 vv = *(const float4*)&V[basebs + (size_t)sk * D_MODEL + lcol];
            *(float4*)&Vs[row * 64 + lcol] = vv;
        }
        __syncthreads();

        // GEMM1: S[qi][ki], 4x4 per thread (qi = ty*4+i, ki = tx*4+j)
        float sreg[4][4];
#pragma unroll
        for (int i = 0; i < 4; i++)
#pragma unroll
            for (int j = 0; j < 4; j++) sreg[i][j] = 0.f;

#pragma unroll 8
        for (int d = 0; d < 64; ++d) {
            float4 aqv = *(const float4*)&Qs[d * 64 + ty * 4];
            float4 bkv = *(const float4*)&Ks[d * 64 + tx * 4];
            float a4[4] = {aqv.x, aqv.y, aqv.z, aqv.w};
            float b4[4] = {bkv.x, bkv.y, bkv.z, bkv.w};
#pragma unroll
            for (int i = 0; i < 4; i++)
#pragma unroll
                for (int j = 0; j < 4; j++)
                    sreg[i][j] = fmaf(a4[i], b4[j], sreg[i][j]);
        }

        // scale, square, causal mask; store P (q-major, float4)
        int qg0 = qt * 64 + ty * 4;
        int kg0 = kt * 64 + tx * 4;
#pragma unroll
        for (int i = 0; i < 4; i++) {
            float p[4];
#pragma unroll
            for (int j = 0; j < 4; j++) {
                float t = sreg[i][j] * inv64;
                t *= t;
                if (kg0 + j > qg0 + i) t = 0.f;
                p[j] = t;
            }
            *(float4*)&Ps[(ty * 4 + i) * 68 + tx * 4] = make_float4(p[0], p[1], p[2], p[3]);
        }
        __syncthreads();

        // GEMM2: Z[qi][d] += sum_kl P[qi][kl] * V[kl][d]
#pragma unroll 8
        for (int kl = 0; kl < 64; ++kl) {
            float4 vv = *(const float4*)&Vs[kl * 64 + tx * 4];
            float p0 = Ps[(ty * 4 + 0) * 68 + kl];
            float p1 = Ps[(ty * 4 + 1) * 68 + kl];
            float p2 = Ps[(ty * 4 + 2) * 68 + kl];
            float p3 = Ps[(ty * 4 + 3) * 68 + kl];
            zacc[0][0] = fmaf(p0, vv.x, zacc[0][0]); zacc[0][1] = fmaf(p0, vv.y, zacc[0][1]);
            zacc[0][2] = fmaf(p0, vv.z, zacc[0][2]); zacc[0][3] = fmaf(p0, vv.w, zacc[0][3]);
            zacc[1][0] = fmaf(p1, vv.x, zacc[1][0]); zacc[1][1] = fmaf(p1, vv.y, zacc[1][1]);
            zacc[1][2] = fmaf(p1, vv.z, zacc[1][2]); zacc[1][3] = fmaf(p1, vv.w, zacc[1][3]);
            zacc[2][0] = fmaf(p2, vv.x, zacc[2][0]); zacc[2][1] = fmaf(p2, vv.y, zacc[2][1]);
            zacc[2][2] = fmaf(p2, vv.z, zacc[2][2]); zacc[2][3] = fmaf(p2, vv.w, zacc[2][3]);
            zacc[3][0] = fmaf(p3, vv.x, zacc[3][0]); zacc[3][1] = fmaf(p3, vv.y, zacc[3][1]);
            zacc[3][2] = fmaf(p3, vv.z, zacc[3][2]); zacc[3][3] = fmaf(p3, vv.w, zacc[3][3]);
        }
    }

    // write Z tile
#pragma unroll
    for (int i = 0; i < 4; i++) {
        int sq = qt * 64 + ty * 4 + i;
        *(float4*)&Z[basebs + (size_t)sq * D_MODEL + tx * 4] =
            make_float4(zacc[i][0], zacc[i][1], zacc[i][2], zacc[i][3]);
    }
}

// ---------------- launch ----------------
extern "C" void kernel_launch(void* const* d_in, const int* in_sizes, int n_in,
                              void* d_out, int out_size)
{
    const float* x  = (const float*)d_in[0];
    const float* Wq = (const float*)d_in[1];
    const float* bq = (const float*)d_in[2];
    const float* Wk = (const float*)d_in[3];
    const float* bk = (const float*)d_in[4];
    const float* Wv = (const float*)d_in[5];
    const float* bv = (const float*)d_in[6];
    const float* Wo = (const float*)d_in[7];
    const float* nw = (const float*)d_in[8];
    float* out = (float*)d_out;

    float *q, *k, *v, *z;
    cudaGetSymbolAddress((void**)&q, g_q);
    cudaGetSymbolAddress((void**)&k, g_k);
    cudaGetSymbolAddress((void**)&v, g_v);
    cudaGetSymbolAddress((void**)&z, g_z);

    rope_cache_kernel<<<64, 1024>>>();

    dim3 gg(D_MODEL / 128, MTOT / 128);
    gemm_nt_kernel<<<gg, 256>>>(x, Wq, bq, nullptr, q, MTOT, D_MODEL, D_MODEL);
    gemm_nt_kernel<<<gg, 256>>>(x, Wk, bk, nullptr, k, MTOT, D_MODEL, D_MODEL);
    gemm_nt_kernel<<<gg, 256>>>(x, Wv, bv, nullptr, v, MTOT, D_MODEL, D_MODEL);

    norm_rope_kernel<<<16384, 256>>>(q, k, nw);

    cudaFuncSetAttribute(attn_kernel, cudaFuncAttributeMaxDynamicSharedMemorySize, ATTN_SMEM);
    attn_kernel<<<dim3(32, 32), 256, ATTN_SMEM>>>(q, k, v, z);

    gemm_nt_kernel<<<gg, 256>>>(z, Wo, nullptr, x, out, MTOT, D_MODEL, D_MODEL);
}

// round 3
// speedup vs baseline: 1.2374x; 1.2374x over previous
#include <cuda_runtime.h>
#include <math.h>
#include <stdint.h>

#define D_MODEL 1024
#define N_HEAD  16
#define D_HEAD  64
#define N_CTX   2048
#define BATCH   2
#define MTOT    (BATCH * N_CTX)   /* 4096 rows */

// ---------------- scratch (static device globals; no allocation) ----------------
__device__ float g_q[MTOT * D_MODEL];
__device__ float g_k[MTOT * D_MODEL];
__device__ float g_v[MTOT * D_MODEL];
__device__ float g_z[MTOT * D_MODEL];
__device__ float g_cos[N_CTX * 32];
__device__ float g_sin[N_CTX * 32];

// ---------------- helpers ----------------
__device__ __forceinline__ float ftf(float x) {
    uint32_t u;
    asm("cvt.rna.tf32.f32 %0, %1;" : "=r"(u) : "f"(x));
    return __uint_as_float(u);
}

__device__ __forceinline__ void mma8(float c[4], const float a[4], const float b[2]) {
    asm volatile(
        "mma.sync.aligned.m16n8k8.row.col.f32.tf32.tf32.f32 "
        "{%0,%1,%2,%3}, {%4,%5,%6,%7}, {%8,%9}, {%0,%1,%2,%3};\n"
        : "+f"(c[0]), "+f"(c[1]), "+f"(c[2]), "+f"(c[3])
        : "r"(__float_as_uint(a[0])), "r"(__float_as_uint(a[1])),
          "r"(__float_as_uint(a[2])), "r"(__float_as_uint(a[3])),
          "r"(__float_as_uint(b[0])), "r"(__float_as_uint(b[1])));
}

// ---------------- RoPE table (fp64 sincos; immune to fast-math) ----------------
__global__ void rope_cache_kernel() {
    int i = blockIdx.x * blockDim.x + threadIdx.x;   // 0 .. 65535
    int t = i >> 5;
    int j = i & 31;
    float invf = (float)pow(10000.0, -(double)j / 32.0);
    double ang = (double)t * (double)invf;
    double sv, cv;
    sincos(ang, &sv, &cv);
    g_cos[i] = (float)cv;
    g_sin[i] = (float)sv;
}

// ---------------- TF32 tensor-core GEMM: C = A * W^T (+bias[n]) (+res) ----------------
// A: [M,K] row-major, W: [N,K] row-major. Block tile 128x128, BK=32.
// 8 warps as 4(M) x 2(N); warp tile 32x64 = 2 m16-tiles x 8 n8-tiles.
// Smem holds operands pre-packed in mma-fragment order:
//   A frag (m16n8k8): a0=(g,t) a1=(g+8,t) a2=(g,t+4) a3=(g+8,t+4), g=lane>>2, t=lane&3
//   B frag:           b0=(k=t,n=g) b1=(k=t+4,n=g)
__global__ __launch_bounds__(256, 2)
void gemm_tc_kernel(const float* __restrict__ A, const float* __restrict__ W,
                    const float* __restrict__ bias, const float* __restrict__ res,
                    float* __restrict__ C, int M, int N, int K)
{
    __shared__ __align__(16) float As[4096];   // [ks(4)][mt(8)][lane(32)][slot(4)]
    __shared__ __align__(16) float Bs[4096];   // [ks(4)][nt(16)][lane(32)][slot(2)]

    const int tid = threadIdx.x;
    const int lane = tid & 31;
    const int wid = tid >> 5;
    const int wm = wid & 3, wn = wid >> 2;        // warp grid 4x2
    const int g = lane >> 2, t = lane & 3;
    const int m0 = blockIdx.y * 128, n0 = blockIdx.x * 128;

    // loader coordinates: each thread loads one row (of A and of W), 16 floats each
    const int lr  = tid >> 1;              // 0..127
    const int lc4 = (tid & 1) * 16;        // 0 or 16
    const float* Ap = A + (size_t)(m0 + lr) * K + lc4;
    const float* Wp = W + (size_t)(n0 + lr) * K + lc4;
    const int amt = lr >> 4, ag = lr & 7, ahi = (lr >> 3) & 1;
    const int bnt = lr >> 3, bg = lr & 7;

    float acc[2][8][4];
#pragma unroll
    for (int mi = 0; mi < 2; mi++)
#pragma unroll
        for (int ni = 0; ni < 8; ni++)
#pragma unroll
            for (int e = 0; e < 4; e++) acc[mi][ni][e] = 0.f;

    for (int kt = 0; kt < K; kt += 32) {
        float4 av[4], wv[4];
#pragma unroll
        for (int i = 0; i < 4; i++) {
            av[i] = *(const float4*)(Ap + kt + 4 * i);
            wv[i] = *(const float4*)(Wp + kt + 4 * i);
        }
        __syncthreads();
#pragma unroll
        for (int i = 0; i < 4; i++) {
            int c0 = lc4 + 4 * i;          // column within the 32-wide chunk
            int ks = c0 >> 3;
            int kh = (c0 >> 2) & 1;
            float* da = &As[(((ks * 8 + amt) * 32) + ag * 4) * 4 + (ahi + 2 * kh)];
            da[0]  = ftf(av[i].x);  // t=0
            da[4]  = ftf(av[i].y);  // t=1
            da[8]  = ftf(av[i].z);  // t=2
            da[12] = ftf(av[i].w);  // t=3
            float* db = &Bs[(((ks * 16 + bnt) * 32) + bg * 4) * 2 + kh];
            db[0] = ftf(wv[i].x);
            db[2] = ftf(wv[i].y);
            db[4] = ftf(wv[i].z);
            db[6] = ftf(wv[i].w);
        }
        __syncthreads();
#pragma unroll
        for (int ks = 0; ks < 4; ks++) {
            float a[2][4];
            float b[8][2];
#pragma unroll
            for (int mi = 0; mi < 2; mi++)
                *(float4*)a[mi] = *(const float4*)&As[((ks * 8 + wm * 2 + mi) * 32 + lane) * 4];
#pragma unroll
            for (int ni = 0; ni < 8; ni++)
                *(float2*)b[ni] = *(const float2*)&Bs[((ks * 16 + wn * 8 + ni) * 32 + lane) * 2];
#pragma unroll
            for (int mi = 0; mi < 2; mi++)
#pragma unroll
                for (int ni = 0; ni < 8; ni++)
                    mma8(acc[mi][ni], a[mi], b[ni]);
        }
    }

    // epilogue: C frag c0=(g,2t) c1=(g,2t+1) c2=(g+8,2t) c3=(g+8,2t+1)
#pragma unroll
    for (int mi = 0; mi < 2; mi++) {
#pragma unroll
        for (int h = 0; h < 2; h++) {
            int m = m0 + wm * 32 + mi * 16 + h * 8 + g;
#pragma unroll
            for (int ni = 0; ni < 8; ni++) {
                int n = n0 + wn * 64 + ni * 8 + 2 * t;
                float2 v = make_float2(acc[mi][ni][h * 2 + 0], acc[mi][ni][h * 2 + 1]);
                if (bias) { v.x += bias[n]; v.y += bias[n + 1]; }
                if (res) {
                    float2 r = *(const float2*)&res[(size_t)m * N + n];
                    v.x += r.x; v.y += r.y;
                }
                *(float2*)&C[(size_t)m * N + n] = v;
            }
        }
    }
}

// ---------------- fused RMSNorm + RoPE, in-place on q and k ----------------
__global__ __launch_bounds__(256)
void norm_rope_kernel(float* __restrict__ q, float* __restrict__ k,
                      const float* __restrict__ w)
{
    int gw = (blockIdx.x * blockDim.x + threadIdx.x) >> 5;
    int lane = threadIdx.x & 31;
    int which = gw & 1;
    int row = gw >> 1;                       // (b*S + s)*H + h
    float* ptr = which ? k : q;

    size_t base = (size_t)(row >> 4) * D_MODEL + (size_t)(row & 15) * 64;
    int s = (row >> 4) & (N_CTX - 1);

    float2 xv = *(float2*)&ptr[base + lane * 2];
    float ss = xv.x * xv.x + xv.y * xv.y;
#pragma unroll
    for (int o = 16; o; o >>= 1) ss += __shfl_xor_sync(0xffffffffu, ss, o);
    float r = rsqrtf(ss * (1.0f / 64.0f) + 1.1920929e-07f);

    float y0 = xv.x * r * w[lane * 2];
    float y1 = xv.y * r * w[lane * 2 + 1];

    int j0 = (2 * lane) & 31;
    int j1 = (2 * lane + 1) & 31;
    float c0 = g_cos[s * 32 + j0], s0 = g_sin[s * 32 + j0];
    float c1 = g_cos[s * 32 + j1], s1 = g_sin[s * 32 + j1];

    float2 o;
    o.x = y0 * c0 - y1 * s0;
    o.y = y1 * c1 + y0 * s1;
    *(float2*)&ptr[base + lane * 2] = o;
}

// ---------------- fused quadratic causal attention (fp32, unchanged) ----------------
#define ATTN_SMEM ((4096 * 3 + 64 * 68) * 4)   /* 66560 B */

__global__ __launch_bounds__(256)
void attn_kernel(const float* __restrict__ Q, const float* __restrict__ Kb,
                 const float* __restrict__ V, float* __restrict__ Z)
{
    extern __shared__ float smf[];
    float* Qs = smf;            // [64][64] d-major
    float* Ks = smf + 4096;     // [64][64] d-major
    float* Vs = smf + 8192;     // [64][64] k-major
    float* Ps = smf + 12288;    // [64][68] q-major

    const int tid = threadIdx.x;
    const int tx = tid & 15, ty = tid >> 4;
    const int bh = blockIdx.y;
    const int b = bh >> 4, h = bh & 15;
    const int qt = (int)gridDim.x - 1 - (int)blockIdx.x;

    const int lrow = tid >> 4;
    const int lcol = (tid & 15) << 2;
    const size_t basebs = (size_t)(b * N_CTX) * D_MODEL + h * 64;

#pragma unroll
    for (int r = 0; r < 4; ++r) {
        int row = lrow + 16 * r;
        int sq = qt * 64 + row;
        float4 qv = *(const float4*)&Q[basebs + (size_t)sq * D_MODEL + lcol];
        Qs[(lcol + 0) * 64 + row] = qv.x;
        Qs[(lcol + 1) * 64 + row] = qv.y;
        Qs[(lcol + 2) * 64 + row] = qv.z;
        Qs[(lcol + 3) * 64 + row] = qv.w;
    }

    float zacc[4][4];
#pragma unroll
    for (int i = 0; i < 4; i++)
#pragma unroll
        for (int j = 0; j < 4; j++) zacc[i][j] = 0.f;

    const float inv64 = 1.0f / 64.0f;

    for (int kt = 0; kt <= qt; ++kt) {
        __syncthreads();
#pragma unroll
        for (int r = 0; r < 4; ++r) {
            int row = lrow + 16 * r;
            int sk = kt * 64 + row;
            float4 kv = *(const float4*)&Kb[basebs + (size_t)sk * D_MODEL + lcol];
            Ks[(lcol + 0) * 64 + row] = kv.x;
            Ks[(lcol + 1) * 64 + row] = kv.y;
            Ks[(lcol + 2) * 64 + row] = kv.z;
            Ks[(lcol + 3) * 64 + row] = kv.w;
            float4 vv = *(const float4*)&V[basebs + (size_t)sk * D_MODEL + lcol];
            *(float4*)&Vs[row * 64 + lcol] = vv;
        }
        __syncthreads();

        float sreg[4][4];
#pragma unroll
        for (int i = 0; i < 4; i++)
#pragma unroll
            for (int j = 0; j < 4; j++) sreg[i][j] = 0.f;

#pragma unroll 8
        for (int d = 0; d < 64; ++d) {
            float4 aqv = *(const float4*)&Qs[d * 64 + ty * 4];
            float4 bkv = *(const float4*)&Ks[d * 64 + tx * 4];
            float a4[4] = {aqv.x, aqv.y, aqv.z, aqv.w};
            float b4[4] = {bkv.x, bkv.y, bkv.z, bkv.w};
#pragma unroll
            for (int i = 0; i < 4; i++)
#pragma unroll
                for (int j = 0; j < 4; j++)
                    sreg[i][j] = fmaf(a4[i], b4[j], sreg[i][j]);
        }

        int qg0 = qt * 64 + ty * 4;
        int kg0 = kt * 64 + tx * 4;
#pragma unroll
        for (int i = 0; i < 4; i++) {
            float p[4];
#pragma unroll
            for (int j = 0; j < 4; j++) {
                float tt = sreg[i][j] * inv64;
                tt *= tt;
                if (kg0 + j > qg0 + i) tt = 0.f;
                p[j] = tt;
            }
            *(float4*)&Ps[(ty * 4 + i) * 68 + tx * 4] = make_float4(p[0], p[1], p[2], p[3]);
        }
        __syncthreads();

#pragma unroll 8
        for (int kl = 0; kl < 64; ++kl) {
            float4 vv = *(const float4*)&Vs[kl * 64 + tx * 4];
            float p0 = Ps[(ty * 4 + 0) * 68 + kl];
            float p1 = Ps[(ty * 4 + 1) * 68 + kl];
            float p2 = Ps[(ty * 4 + 2) * 68 + kl];
            float p3 = Ps[(ty * 4 + 3) * 68 + kl];
            zacc[0][0] = fmaf(p0, vv.x, zacc[0][0]); zacc[0][1] = fmaf(p0, vv.y, zacc[0][1]);
            zacc[0][2] = fmaf(p0, vv.z, zacc[0][2]); zacc[0][3] = fmaf(p0, vv.w, zacc[0][3]);
            zacc[1][0] = fmaf(p1, vv.x, zacc[1][0]); zacc[1][1] = fmaf(p1, vv.y, zacc[1][1]);
            zacc[1][2] = fmaf(p1, vv.z, zacc[1][2]); zacc[1][3] = fmaf(p1, vv.w, zacc[1][3]);
            zacc[2][0] = fmaf(p2, vv.x, zacc[2][0]); zacc[2][1] = fmaf(p2, vv.y, zacc[2][1]);
            zacc[2][2] = fmaf(p2, vv.z, zacc[2][2]); zacc[2][3] = fmaf(p2, vv.w, zacc[2][3]);
            zacc[3][0] = fmaf(p3, vv.x, zacc[3][0]); zacc[3][1] = fmaf(p3, vv.y, zacc[3][1]);
            zacc[3][2] = fmaf(p3, vv.z, zacc[3][2]); zacc[3][3] = fmaf(p3, vv.w, zacc[3][3]);
        }
    }

#pragma unroll
    for (int i = 0; i < 4; i++) {
        int sq = qt * 64 + ty * 4 + i;
        *(float4*)&Z[basebs + (size_t)sq * D_MODEL + tx * 4] =
            make_float4(zacc[i][0], zacc[i][1], zacc[i][2], zacc[i][3]);
    }
}

// ---------------- launch ----------------
extern "C" void kernel_launch(void* const* d_in, const int* in_sizes, int n_in,
                              void* d_out, int out_size)
{
    const float* x  = (const float*)d_in[0];
    const float* Wq = (const float*)d_in[1];
    const float* bq = (const float*)d_in[2];
    const float* Wk = (const float*)d_in[3];
    const float* bk = (const float*)d_in[4];
    const float* Wv = (const float*)d_in[5];
    const float* bv = (const float*)d_in[6];
    const float* Wo = (const float*)d_in[7];
    const float* nw = (const float*)d_in[8];
    float* out = (float*)d_out;

    float *q, *k, *v, *z;
    cudaGetSymbolAddress((void**)&q, g_q);
    cudaGetSymbolAddress((void**)&k, g_k);
    cudaGetSymbolAddress((void**)&v, g_v);
    cudaGetSymbolAddress((void**)&z, g_z);

    rope_cache_kernel<<<64, 1024>>>();

    dim3 gg(D_MODEL / 128, MTOT / 128);
    gemm_tc_kernel<<<gg, 256>>>(x, Wq, bq, nullptr, q, MTOT, D_MODEL, D_MODEL);
    gemm_tc_kernel<<<gg, 256>>>(x, Wk, bk, nullptr, k, MTOT, D_MODEL, D_MODEL);
    gemm_tc_kernel<<<gg, 256>>>(x, Wv, bv, nullptr, v, MTOT, D_MODEL, D_MODEL);

    norm_rope_kernel<<<16384, 256>>>(q, k, nw);

    cudaFuncSetAttribute(attn_kernel, cudaFuncAttributeMaxDynamicSharedMemorySize, ATTN_SMEM);
    attn_kernel<<<dim3(32, 32), 256, ATTN_SMEM>>>(q, k, v, z);

    gemm_tc_kernel<<<gg, 256>>>(z, Wo, nullptr, x, out, MTOT, D_MODEL, D_MODEL);
}

// round 4
// speedup vs baseline: 2.3896x; 1.9310x over previous
#include <cuda_runtime.h>
#include <math.h>
#include <stdint.h>

#define D_MODEL 1024
#define N_HEAD  16
#define D_HEAD  64
#define N_CTX   2048
#define BATCH   2
#define MTOT    (BATCH * N_CTX)   /* 4096 rows */

// ---------------- scratch (static device globals; no allocation) ----------------
__device__ float g_q[MTOT * D_MODEL];
__device__ float g_k[MTOT * D_MODEL];
__device__ float g_v[MTOT * D_MODEL];
__device__ float g_z[MTOT * D_MODEL];
__device__ float g_cos[N_CTX * 32];
__device__ float g_sin[N_CTX * 32];

// ---------------- helpers ----------------
__device__ __forceinline__ float ftf(float x) {
    uint32_t u;
    asm("cvt.rna.tf32.f32 %0, %1;" : "=r"(u) : "f"(x));
    return __uint_as_float(u);
}

__device__ __forceinline__ void mma8(float c[4], const float a[4], const float b[2]) {
    asm volatile(
        "mma.sync.aligned.m16n8k8.row.col.f32.tf32.tf32.f32 "
        "{%0,%1,%2,%3}, {%4,%5,%6,%7}, {%8,%9}, {%0,%1,%2,%3};\n"
        : "+f"(c[0]), "+f"(c[1]), "+f"(c[2]), "+f"(c[3])
        : "r"(__float_as_uint(a[0])), "r"(__float_as_uint(a[1])),
          "r"(__float_as_uint(a[2])), "r"(__float_as_uint(a[3])),
          "r"(__float_as_uint(b[0])), "r"(__float_as_uint(b[1])));
}

// ---------------- RoPE table ----------------
__global__ void rope_cache_kernel() {
    int i = blockIdx.x * blockDim.x + threadIdx.x;   // 0 .. 65535
    int t = i >> 5;
    int j = i & 31;
    float invf = (float)pow(10000.0, -(double)j / 32.0);
    double ang = (double)t * (double)invf;
    double sv, cv;
    sincos(ang, &sv, &cv);
    g_cos[i] = (float)cv;
    g_sin[i] = (float)sv;
}

// ---------------- TF32 tensor-core GEMM: C = A * W^T (+bias[n]) (+res) ----------------
// Block tile 128x128, BK=32. 8 warps as 4(M) x 2(N); warp tile 32x64.
// Fragment-major smem with XOR-by-ks lane swizzle => conflict-free STS.128/LDS.128.
__global__ __launch_bounds__(256, 2)
void gemm_tc_kernel(const float* __restrict__ A, const float* __restrict__ W,
                    const float* __restrict__ bias, const float* __restrict__ res,
                    float* __restrict__ C, int M, int N, int K)
{
    __shared__ __align__(16) float As[4096];   // [ks4][mt8][lane32][slot4]
    __shared__ __align__(16) float Bs[4096];   // [ksp2][nt16][lane32][slot4]
    float4* As4 = (float4*)As;
    float4* Bs4 = (float4*)Bs;

    const int tid = threadIdx.x;
    const int lane = tid & 31;
    const int wid = tid >> 5;
    const int wm = wid & 3, wn = wid >> 2;
    const int m0 = blockIdx.y * 128, n0 = blockIdx.x * 128;

    // A loader: thread owns rows {r, r+8}, cols aks*8..+7 of the 128x32 chunk
    const int amt = tid >> 5, ag = (tid >> 2) & 7, aks = tid & 3;
    const float* Ap = A + (size_t)(m0 + amt * 16 + ag) * K + aks * 8;
    // B loader: thread owns row n, cols bksp*16..+15
    const int bnt = ((tid >> 5) << 1) | (tid & 1);
    const int bg = (tid >> 2) & 7;
    const int bksp = (tid >> 1) & 1;
    const int bxor = bksp | ((bnt & 1) << 1);
    const float* Wp = W + (size_t)(n0 + bnt * 8 + bg) * K + bksp * 16;

    float acc[2][8][4];
#pragma unroll
    for (int mi = 0; mi < 2; mi++)
#pragma unroll
        for (int ni = 0; ni < 8; ni++)
#pragma unroll
            for (int e = 0; e < 4; e++) acc[mi][ni][e] = 0.f;

    for (int kt = 0; kt < K; kt += 32) {
        float a0[4], a1[4], a2[4], a3[4];   // (r,c..), (r,c+4..), (r+8,c..), (r+8,c+4..)
        float w0[4], w1[4], w2[4], w3[4];
        {
            float4 v0 = *(const float4*)(Ap + kt);
            float4 v1 = *(const float4*)(Ap + kt + 4);
            float4 v2 = *(const float4*)(Ap + kt + (size_t)8 * K);
            float4 v3 = *(const float4*)(Ap + kt + (size_t)8 * K + 4);
            a0[0]=v0.x;a0[1]=v0.y;a0[2]=v0.z;a0[3]=v0.w;
            a1[0]=v1.x;a1[1]=v1.y;a1[2]=v1.z;a1[3]=v1.w;
            a2[0]=v2.x;a2[1]=v2.y;a2[2]=v2.z;a2[3]=v2.w;
            a3[0]=v3.x;a3[1]=v3.y;a3[2]=v3.z;a3[3]=v3.w;
            float4 u0 = *(const float4*)(Wp + kt);
            float4 u1 = *(const float4*)(Wp + kt + 4);
            float4 u2 = *(const float4*)(Wp + kt + 8);
            float4 u3 = *(const float4*)(Wp + kt + 12);
            w0[0]=u0.x;w0[1]=u0.y;w0[2]=u0.z;w0[3]=u0.w;
            w1[0]=u1.x;w1[1]=u1.y;w1[2]=u1.z;w1[3]=u1.w;
            w2[0]=u2.x;w2[1]=u2.y;w2[2]=u2.z;w2[3]=u2.w;
            w3[0]=u3.x;w3[1]=u3.y;w3[2]=u3.z;w3[3]=u3.w;
        }
        __syncthreads();
#pragma unroll
        for (int t = 0; t < 4; t++) {
            // A fragment slots: (g,t),(g+8,t),(g,t+4),(g+8,t+4)
            As4[(aks * 8 + amt) * 32 + ag * 4 + (t ^ aks)] =
                make_float4(ftf(a0[t]), ftf(a2[t]), ftf(a1[t]), ftf(a3[t]));
            // B fragment slots (2 ks packed): k=t, t+4, t+8, t+12
            Bs4[(bksp * 16 + bnt) * 32 + bg * 4 + (t ^ bxor)] =
                make_float4(ftf(w0[t]), ftf(w1[t]), ftf(w2[t]), ftf(w3[t]));
        }
        __syncthreads();
#pragma unroll
        for (int ksp = 0; ksp < 2; ksp++) {
            float4 bb[8];
#pragma unroll
            for (int ni = 0; ni < 8; ni++) {
                int nt = wn * 8 + ni;
                int xv = ksp | ((nt & 1) << 1);
                int lp = (lane & ~3) | ((lane & 3) ^ xv);
                bb[ni] = Bs4[(ksp * 16 + nt) * 32 + lp];
            }
#pragma unroll
            for (int kh = 0; kh < 2; kh++) {
                int ks = ksp * 2 + kh;
                int lpa = (lane & ~3) | ((lane & 3) ^ ks);
                float a[2][4];
#pragma unroll
                for (int mi = 0; mi < 2; mi++) {
                    float4 aa = As4[(ks * 8 + wm * 2 + mi) * 32 + lpa];
                    a[mi][0] = aa.x; a[mi][1] = aa.y; a[mi][2] = aa.z; a[mi][3] = aa.w;
                }
#pragma unroll
                for (int mi = 0; mi < 2; mi++)
#pragma unroll
                    for (int ni = 0; ni < 8; ni++) {
                        float b[2];
                        if (kh == 0) { b[0] = bb[ni].x; b[1] = bb[ni].y; }
                        else         { b[0] = bb[ni].z; b[1] = bb[ni].w; }
                        mma8(acc[mi][ni], a[mi], b);
                    }
            }
        }
    }

    const int g = lane >> 2, t = lane & 3;
#pragma unroll
    for (int mi = 0; mi < 2; mi++) {
#pragma unroll
        for (int h = 0; h < 2; h++) {
            int m = m0 + wm * 32 + mi * 16 + h * 8 + g;
#pragma unroll
            for (int ni = 0; ni < 8; ni++) {
                int n = n0 + wn * 64 + ni * 8 + 2 * t;
                float2 v = make_float2(acc[mi][ni][h * 2 + 0], acc[mi][ni][h * 2 + 1]);
                if (bias) { v.x += bias[n]; v.y += bias[n + 1]; }
                if (res) {
                    float2 r = *(const float2*)&res[(size_t)m * N + n];
                    v.x += r.x; v.y += r.y;
                }
                *(float2*)&C[(size_t)m * N + n] = v;
            }
        }
    }
}

// ---------------- fused RMSNorm + RoPE, in-place on q and k ----------------
__global__ __launch_bounds__(256)
void norm_rope_kernel(float* __restrict__ q, float* __restrict__ k,
                      const float* __restrict__ w)
{
    int gw = (blockIdx.x * blockDim.x + threadIdx.x) >> 5;
    int lane = threadIdx.x & 31;
    int which = gw & 1;
    int row = gw >> 1;
    float* ptr = which ? k : q;

    size_t base = (size_t)(row >> 4) * D_MODEL + (size_t)(row & 15) * 64;
    int s = (row >> 4) & (N_CTX - 1);

    float2 xv = *(float2*)&ptr[base + lane * 2];
    float ss = xv.x * xv.x + xv.y * xv.y;
#pragma unroll
    for (int o = 16; o; o >>= 1) ss += __shfl_xor_sync(0xffffffffu, ss, o);
    float r = rsqrtf(ss * (1.0f / 64.0f) + 1.1920929e-07f);

    float y0 = xv.x * r * w[lane * 2];
    float y1 = xv.y * r * w[lane * 2 + 1];

    int j0 = (2 * lane) & 31;
    int j1 = (2 * lane + 1) & 31;
    float c0 = g_cos[s * 32 + j0], s0 = g_sin[s * 32 + j0];
    float c1 = g_cos[s * 32 + j1], s1 = g_sin[s * 32 + j1];

    float2 o;
    o.x = y0 * c0 - y1 * s0;
    o.y = y1 * c1 + y0 * s1;
    *(float2*)&ptr[base + lane * 2] = o;
}

// ---------------- fused quadratic causal attention, TF32 mma ----------------
// Block: one (b, h, q-tile 64). 8 warps = 4(q16) x 2(half-32).
// Smem (floats): Qs 4096 frag-major | Ks 4096 frag-major | Vs 64x68 | Ps 64x68
#define ATTN_SMEM ((4096 + 4096 + 64 * 68 + 64 * 68) * 4)   /* 67584 B */

__global__ __launch_bounds__(256)
void attn_tc_kernel(const float* __restrict__ Q, const float* __restrict__ Kg,
                    const float* __restrict__ V, float* __restrict__ Z)
{
    extern __shared__ float sm[];
    float4* Qs4 = (float4*)sm;               // [qks8][qmt4][lane32][slot4]
    float4* Ks4 = (float4*)(sm + 4096);      // [ksp4][nt8][lane32][slot4]
    float*  Vs  = sm + 8192;                 // [64][68] row-major (tf32 bits)
    float*  Ps  = sm + 8192 + 64 * 68;       // [64][68]

    const int tid = threadIdx.x;
    const int lane = tid & 31;
    const int wid = tid >> 5;
    const int wq = wid & 3, wh = wid >> 2;
    const int g = lane >> 2, t = lane & 3;
    const int bh = blockIdx.y;
    const int b = bh >> 4, h = bh & 15;
    const int qt = (int)gridDim.x - 1 - (int)blockIdx.x;   // big tiles first
    const size_t base = (size_t)(b * N_CTX) * D_MODEL + h * 64;

    // ---- load Q tile into fragment-major smem (once) ----
    {
        int qmt = tid >> 6, qg = (tid >> 3) & 7, qks = tid & 7;
        const float* qp = Q + base + (size_t)(qt * 64 + qmt * 16 + qg) * D_MODEL + qks * 8;
        float4 v0 = *(const float4*)(qp);
        float4 v1 = *(const float4*)(qp + 4);
        float4 v2 = *(const float4*)(qp + (size_t)8 * D_MODEL);
        float4 v3 = *(const float4*)(qp + (size_t)8 * D_MODEL + 4);
        float a0[4] = {v0.x, v0.y, v0.z, v0.w};
        float a1[4] = {v1.x, v1.y, v1.z, v1.w};
        float a2[4] = {v2.x, v2.y, v2.z, v2.w};
        float a3[4] = {v3.x, v3.y, v3.z, v3.w};
#pragma unroll
        for (int tt = 0; tt < 4; tt++)
            Qs4[(qks * 4 + qmt) * 32 + qg * 4 + (tt ^ (qks & 3))] =
                make_float4(ftf(a0[tt]), ftf(a2[tt]), ftf(a1[tt]), ftf(a3[tt]));
    }

    float zacc[4][4];
#pragma unroll
    for (int i = 0; i < 4; i++)
#pragma unroll
        for (int j = 0; j < 4; j++) zacc[i][j] = 0.f;

    const int knt = tid >> 5, kg = (tid >> 2) & 7, kksp = tid & 3;
    const int vrow = tid >> 2, vc = (tid & 3) * 16;
    const float inv64 = 1.0f / 64.0f;

    for (int kt = 0; kt <= qt; ++kt) {
        __syncthreads();   // prev iteration consumers done (also covers Q store, iter 0)
        // ---- K tile -> fragment-major ----
        {
            const float* kp = Kg + base + (size_t)(kt * 64 + knt * 8 + kg) * D_MODEL + kksp * 16;
            float4 u0 = *(const float4*)(kp);
            float4 u1 = *(const float4*)(kp + 4);
            float4 u2 = *(const float4*)(kp + 8);
            float4 u3 = *(const float4*)(kp + 12);
            float w0[4] = {u0.x, u0.y, u0.z, u0.w};
            float w1[4] = {u1.x, u1.y, u1.z, u1.w};
            float w2[4] = {u2.x, u2.y, u2.z, u2.w};
            float w3[4] = {u3.x, u3.y, u3.z, u3.w};
#pragma unroll
            for (int tt = 0; tt < 4; tt++)
                Ks4[(kksp * 8 + knt) * 32 + kg * 4 + (tt ^ kksp)] =
                    make_float4(ftf(w0[tt]), ftf(w1[tt]), ftf(w2[tt]), ftf(w3[tt]));
        }
        // ---- V tile -> row-major stride 68 (tf32 bits) ----
        {
            const float* vp = V + base + (size_t)(kt * 64 + vrow) * D_MODEL + vc;
#pragma unroll
            for (int i = 0; i < 4; i++) {
                float4 vv = *(const float4*)(vp + 4 * i);
                *(float4*)&Vs[vrow * 68 + vc + 4 * i] =
                    make_float4(ftf(vv.x), ftf(vv.y), ftf(vv.z), ftf(vv.w));
            }
        }
        __syncthreads();

        // ---- GEMM1: S[16q x 32k] per warp ----
        float sacc[4][4];
#pragma unroll
        for (int i = 0; i < 4; i++)
#pragma unroll
            for (int j = 0; j < 4; j++) sacc[i][j] = 0.f;

#pragma unroll
        for (int ksp = 0; ksp < 4; ksp++) {
            float4 kb[4];
#pragma unroll
            for (int ni = 0; ni < 4; ni++) {
                int nt = wh * 4 + ni;
                int lp = (lane & ~3) | ((lane & 3) ^ ksp);
                kb[ni] = Ks4[(ksp * 8 + nt) * 32 + lp];
            }
#pragma unroll
            for (int kh = 0; kh < 2; kh++) {
                int ks = ksp * 2 + kh;
                int lpq = (lane & ~3) | ((lane & 3) ^ (ks & 3));
                float4 qa = Qs4[(ks * 4 + wq) * 32 + lpq];
                float a[4] = {qa.x, qa.y, qa.z, qa.w};
#pragma unroll
                for (int ni = 0; ni < 4; ni++) {
                    float bfr[2];
                    if (kh == 0) { bfr[0] = kb[ni].x; bfr[1] = kb[ni].y; }
                    else         { bfr[0] = kb[ni].z; bfr[1] = kb[ni].w; }
                    mma8(sacc[ni], a, bfr);
                }
            }
        }

        // ---- scale, square, causal mask; store P (tf32 bits) ----
        {
            int q0 = qt * 64 + wq * 16 + g;
            int q1 = q0 + 8;
#pragma unroll
            for (int ni = 0; ni < 4; ni++) {
                int kk = kt * 64 + wh * 32 + ni * 8 + 2 * t;
                float p0 = sacc[ni][0] * inv64; p0 *= p0; if (kk > q0)     p0 = 0.f;
                float p1 = sacc[ni][1] * inv64; p1 *= p1; if (kk + 1 > q0) p1 = 0.f;
                float p2 = sacc[ni][2] * inv64; p2 *= p2; if (kk > q1)     p2 = 0.f;
                float p3 = sacc[ni][3] * inv64; p3 *= p3; if (kk + 1 > q1) p3 = 0.f;
                int col = wh * 32 + ni * 8 + 2 * t;
                *(float2*)&Ps[(wq * 16 + g) * 68 + col]     = make_float2(ftf(p0), ftf(p1));
                *(float2*)&Ps[(wq * 16 + g + 8) * 68 + col] = make_float2(ftf(p2), ftf(p3));
            }
        }
        __syncthreads();

        // ---- GEMM2: Z[16q x 32d] += P * V ----
#pragma unroll
        for (int ks = 0; ks < 8; ks++) {
            int col = ks * 8 + t;
            float a[4];
            a[0] = Ps[(wq * 16 + g) * 68 + col];
            a[1] = Ps[(wq * 16 + g + 8) * 68 + col];
            a[2] = Ps[(wq * 16 + g) * 68 + col + 4];
            a[3] = Ps[(wq * 16 + g + 8) * 68 + col + 4];
#pragma unroll
            for (int ni = 0; ni < 4; ni++) {
                int d0 = wh * 32 + ni * 8 + g;
                float bfr[2];
                bfr[0] = Vs[(ks * 8 + t) * 68 + d0];
                bfr[1] = Vs[(ks * 8 + t + 4) * 68 + d0];
                mma8(zacc[ni], a, bfr);
            }
        }
    }

    // ---- write Z tile ----
#pragma unroll
    for (int ni = 0; ni < 4; ni++) {
        int col = wh * 32 + ni * 8 + 2 * t;
        int r0 = qt * 64 + wq * 16 + g;
        *(float2*)&Z[base + (size_t)r0 * D_MODEL + col] =
            make_float2(zacc[ni][0], zacc[ni][1]);
        *(float2*)&Z[base + (size_t)(r0 + 8) * D_MODEL + col] =
            make_float2(zacc[ni][2], zacc[ni][3]);
    }
}

// ---------------- launch ----------------
extern "C" void kernel_launch(void* const* d_in, const int* in_sizes, int n_in,
                              void* d_out, int out_size)
{
    const float* x  = (const float*)d_in[0];
    const float* Wq = (const float*)d_in[1];
    const float* bq = (const float*)d_in[2];
    const float* Wk = (const float*)d_in[3];
    const float* bk = (const float*)d_in[4];
    const float* Wv = (const float*)d_in[5];
    const float* bv = (const float*)d_in[6];
    const float* Wo = (const float*)d_in[7];
    const float* nw = (const float*)d_in[8];
    float* out = (float*)d_out;

    float *q, *k, *v, *z;
    cudaGetSymbolAddress((void**)&q, g_q);
    cudaGetSymbolAddress((void**)&k, g_k);
    cudaGetSymbolAddress((void**)&v, g_v);
    cudaGetSymbolAddress((void**)&z, g_z);

    rope_cache_kernel<<<64, 1024>>>();

    dim3 gg(D_MODEL / 128, MTOT / 128);
    gemm_tc_kernel<<<gg, 256>>>(x, Wq, bq, nullptr, q, MTOT, D_MODEL, D_MODEL);
    gemm_tc_kernel<<<gg, 256>>>(x, Wk, bk, nullptr, k, MTOT, D_MODEL, D_MODEL);
    gemm_tc_kernel<<<gg, 256>>>(x, Wv, bv, nullptr, v, MTOT, D_MODEL, D_MODEL);

    norm_rope_kernel<<<16384, 256>>>(q, k, nw);

    cudaFuncSetAttribute(attn_tc_kernel, cudaFuncAttributeMaxDynamicSharedMemorySize, ATTN_SMEM);
    attn_tc_kernel<<<dim3(32, 32), 256, ATTN_SMEM>>>(q, k, v, z);

    gemm_tc_kernel<<<gg, 256>>>(z, Wo, nullptr, x, out, MTOT, D_MODEL, D_MODEL);
}